// round 4
// baseline (speedup 1.0000x reference)
#include <cuda_runtime.h>
#include <cstdint>
#include <cstddef>

#define D 128
#define MAXN 100000
#define MAXE 1600000
#define BM 64
#define RSTR 65          // float stride, odd => conflict-free fills

typedef unsigned long long u64;

__device__ u64 g_edges[MAXE];
__device__ int g_cnt[MAXN];
__device__ int g_row[MAXN + 1];
__device__ int g_cur[MAXN];
__device__ int g_is64;

__device__ __forceinline__ u64 dup2(float f) {
    u64 r; unsigned u = __float_as_uint(f);
    asm("mov.b64 %0, {%1, %1};" : "=l"(r) : "r"(u));
    return r;
}
__device__ __forceinline__ void ffma2(u64& d, u64 a, u64 b) {
    asm("fma.rn.f32x2 %0, %1, %2, %0;" : "+l"(d) : "l"(a), "l"(b));
}
__device__ __forceinline__ u64 add2(u64 a, u64 b) {
    u64 r;
    asm("add.rn.f32x2 %0, %1, %2;" : "=l"(r) : "l"(a), "l"(b));
    return r;
}

__global__ void zero_cnt_kernel(const int* __restrict__ idx_raw, int n) {
    int i = blockIdx.x * blockDim.x + threadIdx.x;
    if (i < n) g_cnt[i] = 0;
    if (i == 0) {
        unsigned o = 0;
        #pragma unroll
        for (int j = 0; j < 16; j++) o |= (unsigned)idx_raw[2 * j + 1];
        g_is64 = (o == 0u) ? 1 : 0;
    }
}

__global__ void hist_kernel(const int* __restrict__ dst_raw, int E) {
    const bool is64 = (g_is64 != 0);
    int e = blockIdx.x * blockDim.x + threadIdx.x;
    if (e >= E) return;
    int d = is64 ? (int)((const long long*)dst_raw)[e] : dst_raw[e];
    atomicAdd(&g_cnt[d], 1);
}

__global__ void __launch_bounds__(1024) scan_kernel(int n, int E) {
    __shared__ int ssum[1024];
    const int tid = threadIdx.x;
    const int chunk = (n + 1023) >> 10;
    const int beg = tid * chunk;
    const int end = min(beg + chunk, n);

    int s = 0;
    for (int i = beg; i < end; i++) s += g_cnt[i];
    ssum[tid] = s;
    __syncthreads();
    for (int off = 1; off < 1024; off <<= 1) {
        int v = (tid >= off) ? ssum[tid - off] : 0;
        __syncthreads();
        ssum[tid] += v;
        __syncthreads();
    }
    int run = (tid > 0) ? ssum[tid - 1] : 0;
    for (int i = beg; i < end; i++) {
        int c = g_cnt[i];
        g_row[i] = run;
        g_cur[i] = run;
        run += c;
    }
    if (tid == 1023) g_row[n] = E;
}

__global__ void scatter_kernel(const int* __restrict__ src_raw,
                               const int* __restrict__ dst_raw,
                               const float* __restrict__ w, int E) {
    const bool is64 = (g_is64 != 0);
    int t = blockIdx.x * blockDim.x + threadIdx.x;
    int e = t * 2;
    if (e >= E) return;
    int cnt = min(2, E - e);
    #pragma unroll
    for (int j = 0; j < 2; j++) {
        if (j >= cnt) break;
        int s, d;
        if (is64) {
            s = (int)((const long long*)src_raw)[e + j];
            d = (int)((const long long*)dst_raw)[e + j];
        } else {
            s = src_raw[e + j];
            d = dst_raw[e + j];
        }
        float ww = w[e + j];
        int pos = atomicAdd(&g_cur[d], 1);
        g_edges[pos] = ((u64)__float_as_uint(ww) << 32) | (unsigned)s;
    }
}

__global__ void __launch_bounds__(256, 2) fused_kernel(
    const float* __restrict__ x,
    const float* __restrict__ Wn,
    const float* __restrict__ Ws,
    const float* __restrict__ bias,
    float* __restrict__ out,
    int n)
{
    extern __shared__ float sm[];
    float* s_a = sm;                  // [128][RSTR]
    float* s_x = sm + 128 * RSTR;

    const int tid  = threadIdx.x;
    const int wid  = tid >> 5;
    const int lane = tid & 31;
    const int row0 = blockIdx.x * BM;

    // phase 1a: x-tile copy
    for (int idx = tid; idx < BM * D; idx += 256) {
        int r = idx >> 7;
        int k = idx & 127;
        int gr = row0 + r;
        if (gr < n) s_x[k * RSTR + r] = x[(size_t)gr * D + k];
    }

    // phase 1b: CSR gather-aggregate into A-tile
    {
        const float4* x4 = (const float4*)x;
        #pragma unroll 1
        for (int j = 0; j < 8; j++) {
            int r = wid * 8 + j;
            int node = row0 + r;
            if (node >= n) break;
            int beg = g_row[node];
            int end = g_row[node + 1];

            float4 a0 = make_float4(0.f, 0.f, 0.f, 0.f);
            float4 a1 = make_float4(0.f, 0.f, 0.f, 0.f);
            float4 a2 = make_float4(0.f, 0.f, 0.f, 0.f);
            float4 a3 = make_float4(0.f, 0.f, 0.f, 0.f);
            int i = beg;
            for (; i + 3 < end; i += 4) {
                u64 e0 = g_edges[i];
                u64 e1 = g_edges[i + 1];
                u64 e2 = g_edges[i + 2];
                u64 e3 = g_edges[i + 3];
                float4 v0 = __ldg(&x4[(size_t)(unsigned)e0 * (D / 4) + lane]);
                float4 v1 = __ldg(&x4[(size_t)(unsigned)e1 * (D / 4) + lane]);
                float4 v2 = __ldg(&x4[(size_t)(unsigned)e2 * (D / 4) + lane]);
                float4 v3 = __ldg(&x4[(size_t)(unsigned)e3 * (D / 4) + lane]);
                float w0 = __uint_as_float((unsigned)(e0 >> 32));
                float w1 = __uint_as_float((unsigned)(e1 >> 32));
                float w2 = __uint_as_float((unsigned)(e2 >> 32));
                float w3 = __uint_as_float((unsigned)(e3 >> 32));
                a0.x += w0 * v0.x; a0.y += w0 * v0.y; a0.z += w0 * v0.z; a0.w += w0 * v0.w;
                a1.x += w1 * v1.x; a1.y += w1 * v1.y; a1.z += w1 * v1.z; a1.w += w1 * v1.w;
                a2.x += w2 * v2.x; a2.y += w2 * v2.y; a2.z += w2 * v2.z; a2.w += w2 * v2.w;
                a3.x += w3 * v3.x; a3.y += w3 * v3.y; a3.z += w3 * v3.z; a3.w += w3 * v3.w;
            }
            for (; i < end; i++) {
                u64 e0 = g_edges[i];
                float w0 = __uint_as_float((unsigned)(e0 >> 32));
                float4 v0 = __ldg(&x4[(size_t)(unsigned)e0 * (D / 4) + lane]);
                a0.x += w0 * v0.x; a0.y += w0 * v0.y; a0.z += w0 * v0.z; a0.w += w0 * v0.w;
            }
            float4 rr;
            rr.x = (a0.x + a1.x) + (a2.x + a3.x);
            rr.y = (a0.y + a1.y) + (a2.y + a3.y);
            rr.z = (a0.z + a1.z) + (a2.z + a3.z);
            rr.w = (a0.w + a1.w) + (a2.w + a3.w);
            s_a[(4 * lane + 0) * RSTR + r] = rr.x;
            s_a[(4 * lane + 1) * RSTR + r] = rr.y;
            s_a[(4 * lane + 2) * RSTR + r] = rr.z;
            s_a[(4 * lane + 3) * RSTR + r] = rr.w;
        }
    }
    __syncthreads();

    // phase 2: dual GEMM; warp = 16 cols, lane = row pair
    const int c0 = wid * 16;
    const int r0 = lane * 2;

    u64 acc0[8], acc1[8];
    #pragma unroll
    for (int c = 0; c < 8; c++) { acc0[c] = 0ull; acc1[c] = 0ull; }

    #pragma unroll 2
    for (int k = 0; k < 128; k++) {
        float a0f = s_a[k * RSTR + r0];
        float a1f = s_a[k * RSTR + r0 + 1];
        float x0f = s_x[k * RSTR + r0];
        float x1f = s_x[k * RSTR + r0 + 1];
        u64 A0 = dup2(a0f), A1 = dup2(a1f);
        u64 X0 = dup2(x0f), X1 = dup2(x1f);

        const ulonglong2* pn = (const ulonglong2*)(Wn + (size_t)k * D + c0);
        const ulonglong2* ps = (const ulonglong2*)(Ws + (size_t)k * D + c0);
        ulonglong2 n01 = __ldg(pn);
        ulonglong2 n23 = __ldg(pn + 1);
        ulonglong2 n45 = __ldg(pn + 2);
        ulonglong2 n67 = __ldg(pn + 3);
        ulonglong2 s01 = __ldg(ps);
        ulonglong2 s23 = __ldg(ps + 1);
        ulonglong2 s45 = __ldg(ps + 2);
        ulonglong2 s67 = __ldg(ps + 3);

        ffma2(acc0[0], A0, n01.x); ffma2(acc0[0], X0, s01.x);
        ffma2(acc0[1], A0, n01.y); ffma2(acc0[1], X0, s01.y);
        ffma2(acc0[2], A0, n23.x); ffma2(acc0[2], X0, s23.x);
        ffma2(acc0[3], A0, n23.y); ffma2(acc0[3], X0, s23.y);
        ffma2(acc0[4], A0, n45.x); ffma2(acc0[4], X0, s45.x);
        ffma2(acc0[5], A0, n45.y); ffma2(acc0[5], X0, s45.y);
        ffma2(acc0[6], A0, n67.x); ffma2(acc0[6], X0, s67.x);
        ffma2(acc0[7], A0, n67.y); ffma2(acc0[7], X0, s67.y);

        ffma2(acc1[0], A1, n01.x); ffma2(acc1[0], X1, s01.x);
        ffma2(acc1[1], A1, n01.y); ffma2(acc1[1], X1, s01.y);
        ffma2(acc1[2], A1, n23.x); ffma2(acc1[2], X1, s23.x);
        ffma2(acc1[3], A1, n23.y); ffma2(acc1[3], X1, s23.y);
        ffma2(acc1[4], A1, n45.x); ffma2(acc1[4], X1, s45.x);
        ffma2(acc1[5], A1, n45.y); ffma2(acc1[5], X1, s45.y);
        ffma2(acc1[6], A1, n67.x); ffma2(acc1[6], X1, s67.x);
        ffma2(acc1[7], A1, n67.y); ffma2(acc1[7], X1, s67.y);
    }

    u64 b[8];
    #pragma unroll
    for (int c = 0; c < 8; c++) b[c] = *(const u64*)(bias + c0 + 2 * c);

    int rlo = row0 + r0;
    if (rlo < n) {
        float* op = out + (size_t)rlo * D + c0;
        #pragma unroll
        for (int c = 0; c < 8; c += 2) {
            ulonglong2 st;
            st.x = add2(acc0[c], b[c]);
            st.y = add2(acc0[c + 1], b[c + 1]);
            *(ulonglong2*)(op + 2 * c) = st;
        }
    }
    if (rlo + 1 < n) {
        float* op = out + (size_t)(rlo + 1) * D + c0;
        #pragma unroll
        for (int c = 0; c < 8; c += 2) {
            ulonglong2 st;
            st.x = add2(acc1[c], b[c]);
            st.y = add2(acc1[c + 1], b[c + 1]);
            *(ulonglong2*)(op + 2 * c) = st;
        }
    }
}

extern "C" void kernel_launch(void* const* d_in, const int* in_sizes, int n_in,
                              void* d_out, int out_size) {
    const float* x    = (const float*)d_in[0];
    const int*   src  = (const int*)d_in[1];
    const int*   dst  = (const int*)d_in[2];
    const float* w    = (const float*)d_in[3];
    const float* Wn   = (const float*)d_in[4];
    const float* Ws   = (const float*)d_in[5];
    const float* bias = (const float*)d_in[6];
    float* out = (float*)d_out;

    const int n = in_sizes[0] / D;
    const int E = in_sizes[3];
    const int blk = 256;

    zero_cnt_kernel<<<(n + blk - 1) / blk, blk>>>(src, n);
    hist_kernel<<<(E + blk - 1) / blk, blk>>>(dst, E);
    scan_kernel<<<1, 1024>>>(n, E);
    {
        int nt = (E + 1) / 2;
        scatter_kernel<<<(nt + blk - 1) / blk, blk>>>(src, dst, w, E);
    }
    {
        size_t smem = 2ull * 128 * RSTR * sizeof(float);  // 66,560 B
        cudaFuncSetAttribute(fused_kernel,
                             cudaFuncAttributeMaxDynamicSharedMemorySize,
                             (int)smem);
        int grid = (n + BM - 1) / BM;
        fused_kernel<<<grid, 256, smem>>>(x, Wn, Ws, bias, out, n);
    }
}

// round 5
// speedup vs baseline: 1.0451x; 1.0451x over previous
#include <cuda_runtime.h>
#include <cstdint>
#include <cstddef>

#define D 128
#define MAXN 100000
#define MAXE 1600000
#define BM 64
#define RSTR 66          // float stride: row-pairs are 8B-aligned & LDS.64 conflict-free

typedef unsigned long long u64;

// ---------------------------------------------------------------------------
// Device scratch (static; allocation-guard-safe)
// ---------------------------------------------------------------------------
__device__ float g_agg[(size_t)MAXN * D];      // aggregated neighbor rows
__device__ u64   g_edges[MAXE];                // packed (w<<32 | src), CSR order
__device__ int   g_cnt[MAXN];
__device__ int   g_row[MAXN + 1];
__device__ int   g_cur[MAXN];
__device__ int   g_is64;

// ---------------------------------------------------------------------------
// f32x2 helpers
// ---------------------------------------------------------------------------
__device__ __forceinline__ u64 dup2(float f) {
    u64 r; unsigned u = __float_as_uint(f);
    asm("mov.b64 %0, {%1, %1};" : "=l"(r) : "r"(u));
    return r;
}
__device__ __forceinline__ void ffma2(u64& d, u64 a, u64 b) {
    asm("fma.rn.f32x2 %0, %1, %2, %0;" : "+l"(d) : "l"(a), "l"(b));
}
__device__ __forceinline__ u64 add2(u64 a, u64 b) {
    u64 r;
    asm("add.rn.f32x2 %0, %1, %2;" : "=l"(r) : "l"(a), "l"(b));
    return r;
}
__device__ __forceinline__ float2 split2(u64 v) {
    unsigned lo, hi;
    asm("mov.b64 {%0, %1}, %2;" : "=r"(lo), "=r"(hi) : "l"(v));
    float2 r; r.x = __uint_as_float(lo); r.y = __uint_as_float(hi);
    return r;
}

// ---------------------------------------------------------------------------
// CSR build kernels
// ---------------------------------------------------------------------------
__global__ void zero_cnt_kernel(const int* __restrict__ idx_raw, int n) {
    int i = blockIdx.x * blockDim.x + threadIdx.x;
    if (i < n) g_cnt[i] = 0;
    if (i == 0) {
        unsigned o = 0;
        #pragma unroll
        for (int j = 0; j < 16; j++) o |= (unsigned)idx_raw[2 * j + 1];
        g_is64 = (o == 0u) ? 1 : 0;
    }
}

__global__ void hist_kernel(const int* __restrict__ dst_raw, int E) {
    const bool is64 = (g_is64 != 0);
    int e = blockIdx.x * blockDim.x + threadIdx.x;
    if (e >= E) return;
    int d = is64 ? (int)((const long long*)dst_raw)[e] : dst_raw[e];
    atomicAdd(&g_cnt[d], 1);
}

__global__ void __launch_bounds__(1024) scan_kernel(int n, int E) {
    __shared__ int ssum[1024];
    const int tid = threadIdx.x;
    const int chunk = (n + 1023) >> 10;
    const int beg = tid * chunk;
    const int end = min(beg + chunk, n);

    int s = 0;
    for (int i = beg; i < end; i++) s += g_cnt[i];
    ssum[tid] = s;
    __syncthreads();
    for (int off = 1; off < 1024; off <<= 1) {
        int v = (tid >= off) ? ssum[tid - off] : 0;
        __syncthreads();
        ssum[tid] += v;
        __syncthreads();
    }
    int run = (tid > 0) ? ssum[tid - 1] : 0;
    for (int i = beg; i < end; i++) {
        int c = g_cnt[i];
        g_row[i] = run;
        g_cur[i] = run;
        run += c;
    }
    if (tid == 1023) g_row[n] = E;
}

__global__ void scatter_kernel(const int* __restrict__ src_raw,
                               const int* __restrict__ dst_raw,
                               const float* __restrict__ w, int E) {
    const bool is64 = (g_is64 != 0);
    int t = blockIdx.x * blockDim.x + threadIdx.x;
    int e = t * 2;
    if (e >= E) return;
    int cnt = min(2, E - e);
    #pragma unroll
    for (int j = 0; j < 2; j++) {
        if (j >= cnt) break;
        int s, d;
        if (is64) {
            s = (int)((const long long*)src_raw)[e + j];
            d = (int)((const long long*)dst_raw)[e + j];
        } else {
            s = src_raw[e + j];
            d = dst_raw[e + j];
        }
        float ww = w[e + j];
        int pos = atomicAdd(&g_cur[d], 1);
        g_edges[pos] = ((u64)__float_as_uint(ww) << 32) | (unsigned)s;
    }
}

// ---------------------------------------------------------------------------
// Aggregation: one warp per dst node, 4-deep MLP, register accumulate.
// ---------------------------------------------------------------------------
__global__ void __launch_bounds__(256) agg_kernel(const float* __restrict__ x, int n) {
    const int warp = (blockIdx.x * blockDim.x + threadIdx.x) >> 5;
    if (warp >= n) return;
    const int lane = threadIdx.x & 31;

    const int beg = g_row[warp];
    const int end = g_row[warp + 1];
    const float4* x4 = (const float4*)x;

    float4 a0 = make_float4(0.f, 0.f, 0.f, 0.f);
    float4 a1 = make_float4(0.f, 0.f, 0.f, 0.f);
    float4 a2 = make_float4(0.f, 0.f, 0.f, 0.f);
    float4 a3 = make_float4(0.f, 0.f, 0.f, 0.f);

    int i = beg;
    for (; i + 3 < end; i += 4) {
        u64 e0 = g_edges[i];
        u64 e1 = g_edges[i + 1];
        u64 e2 = g_edges[i + 2];
        u64 e3 = g_edges[i + 3];
        float4 v0 = __ldg(&x4[(size_t)(unsigned)e0 * (D / 4) + lane]);
        float4 v1 = __ldg(&x4[(size_t)(unsigned)e1 * (D / 4) + lane]);
        float4 v2 = __ldg(&x4[(size_t)(unsigned)e2 * (D / 4) + lane]);
        float4 v3 = __ldg(&x4[(size_t)(unsigned)e3 * (D / 4) + lane]);
        float w0 = __uint_as_float((unsigned)(e0 >> 32));
        float w1 = __uint_as_float((unsigned)(e1 >> 32));
        float w2 = __uint_as_float((unsigned)(e2 >> 32));
        float w3 = __uint_as_float((unsigned)(e3 >> 32));
        a0.x += w0 * v0.x; a0.y += w0 * v0.y; a0.z += w0 * v0.z; a0.w += w0 * v0.w;
        a1.x += w1 * v1.x; a1.y += w1 * v1.y; a1.z += w1 * v1.z; a1.w += w1 * v1.w;
        a2.x += w2 * v2.x; a2.y += w2 * v2.y; a2.z += w2 * v2.z; a2.w += w2 * v2.w;
        a3.x += w3 * v3.x; a3.y += w3 * v3.y; a3.z += w3 * v3.z; a3.w += w3 * v3.w;
    }
    for (; i < end; i++) {
        u64 e0 = g_edges[i];
        float w0 = __uint_as_float((unsigned)(e0 >> 32));
        float4 v0 = __ldg(&x4[(size_t)(unsigned)e0 * (D / 4) + lane]);
        a0.x += w0 * v0.x; a0.y += w0 * v0.y; a0.z += w0 * v0.z; a0.w += w0 * v0.w;
    }
    float4 r;
    r.x = (a0.x + a1.x) + (a2.x + a3.x);
    r.y = (a0.y + a1.y) + (a2.y + a3.y);
    r.z = (a0.z + a1.z) + (a2.z + a3.z);
    r.w = (a0.w + a1.w) + (a2.w + a3.w);
    ((float4*)g_agg)[(size_t)warp * (D / 4) + lane] = r;
}

// ---------------------------------------------------------------------------
// Single-GEMM template body: acc = M_tile @ W  (column-pair f32x2)
// warp = 16 cols, lane = row pair (LDS.64). Weight LDGs are warp-uniform.
// ---------------------------------------------------------------------------
__device__ __forceinline__ void gemm_core(
    const float* __restrict__ s_m,   // smem tile [128][RSTR]
    const float* __restrict__ W,     // [128][128] row-major
    int c0, int r0, u64 acc0[8], u64 acc1[8])
{
    #pragma unroll 2
    for (int k = 0; k < 128; k++) {
        u64 mp = *(const u64*)(s_m + k * RSTR + r0);   // {m[r0], m[r0+1]}
        float2 mv = split2(mp);
        u64 M0 = dup2(mv.x), M1 = dup2(mv.y);

        const ulonglong2* pw = (const ulonglong2*)(W + (size_t)k * D + c0);
        ulonglong2 w01 = __ldg(pw);        // col pairs 0,1
        ulonglong2 w23 = __ldg(pw + 1);    // col pairs 2,3
        ulonglong2 w45 = __ldg(pw + 2);
        ulonglong2 w67 = __ldg(pw + 3);

        ffma2(acc0[0], M0, w01.x); ffma2(acc1[0], M1, w01.x);
        ffma2(acc0[1], M0, w01.y); ffma2(acc1[1], M1, w01.y);
        ffma2(acc0[2], M0, w23.x); ffma2(acc1[2], M1, w23.x);
        ffma2(acc0[3], M0, w23.y); ffma2(acc1[3], M1, w23.y);
        ffma2(acc0[4], M0, w45.x); ffma2(acc1[4], M1, w45.x);
        ffma2(acc0[5], M0, w45.y); ffma2(acc1[5], M1, w45.y);
        ffma2(acc0[6], M0, w67.x); ffma2(acc1[6], M1, w67.x);
        ffma2(acc0[7], M0, w67.y); ffma2(acc1[7], M1, w67.y);
    }
}

// ---------------------------------------------------------------------------
// self_gemm: out = x @ Ws + bias          (runs on side stream)
// ---------------------------------------------------------------------------
__global__ void __launch_bounds__(256) self_gemm_kernel(
    const float* __restrict__ x,
    const float* __restrict__ Ws,
    const float* __restrict__ bias,
    float* __restrict__ out, int n)
{
    __shared__ float s_m[128 * RSTR];
    const int tid = threadIdx.x;
    const int row0 = blockIdx.x * BM;

    for (int idx = tid; idx < BM * D; idx += 256) {
        int r = idx >> 7;
        int k = idx & 127;
        int gr = row0 + r;
        s_m[k * RSTR + r] = (gr < n) ? x[(size_t)gr * D + k] : 0.f;
    }
    __syncthreads();

    const int c0 = (tid >> 5) * 16;
    const int r0 = (tid & 31) * 2;

    u64 acc0[8], acc1[8];
    #pragma unroll
    for (int c = 0; c < 8; c++) { acc0[c] = 0ull; acc1[c] = 0ull; }
    gemm_core(s_m, Ws, c0, r0, acc0, acc1);

    u64 b[8];
    #pragma unroll
    for (int c = 0; c < 8; c++) b[c] = *(const u64*)(bias + c0 + 2 * c);

    int rlo = row0 + r0;
    if (rlo < n) {
        float* op = out + (size_t)rlo * D + c0;
        #pragma unroll
        for (int c = 0; c < 8; c += 2) {
            ulonglong2 st;
            st.x = add2(acc0[c], b[c]);
            st.y = add2(acc0[c + 1], b[c + 1]);
            *(ulonglong2*)(op + 2 * c) = st;
        }
    }
    if (rlo + 1 < n) {
        float* op = out + (size_t)(rlo + 1) * D + c0;
        #pragma unroll
        for (int c = 0; c < 8; c += 2) {
            ulonglong2 st;
            st.x = add2(acc1[c], b[c]);
            st.y = add2(acc1[c + 1], b[c + 1]);
            *(ulonglong2*)(op + 2 * c) = st;
        }
    }
}

// ---------------------------------------------------------------------------
// nbrs_gemm: out += g_agg @ Wn           (after agg AND self_gemm)
// ---------------------------------------------------------------------------
__global__ void __launch_bounds__(256) nbrs_gemm_kernel(
    const float* __restrict__ Wn,
    float* __restrict__ out, int n)
{
    __shared__ float s_m[128 * RSTR];
    const int tid = threadIdx.x;
    const int row0 = blockIdx.x * BM;

    for (int idx = tid; idx < BM * D; idx += 256) {
        int r = idx >> 7;
        int k = idx & 127;
        int gr = row0 + r;
        s_m[k * RSTR + r] = (gr < n) ? g_agg[(size_t)gr * D + k] : 0.f;
    }
    __syncthreads();

    const int c0 = (tid >> 5) * 16;
    const int r0 = (tid & 31) * 2;

    u64 acc0[8], acc1[8];
    #pragma unroll
    for (int c = 0; c < 8; c++) { acc0[c] = 0ull; acc1[c] = 0ull; }
    gemm_core(s_m, Wn, c0, r0, acc0, acc1);

    int rlo = row0 + r0;
    if (rlo < n) {
        float* op = out + (size_t)rlo * D + c0;
        #pragma unroll
        for (int c = 0; c < 8; c += 2) {
            ulonglong2 cur = *(const ulonglong2*)(op + 2 * c);
            ulonglong2 st;
            st.x = add2(acc0[c], cur.x);
            st.y = add2(acc0[c + 1], cur.y);
            *(ulonglong2*)(op + 2 * c) = st;
        }
    }
    if (rlo + 1 < n) {
        float* op = out + (size_t)(rlo + 1) * D + c0;
        #pragma unroll
        for (int c = 0; c < 8; c += 2) {
            ulonglong2 cur = *(const ulonglong2*)(op + 2 * c);
            ulonglong2 st;
            st.x = add2(acc1[c], cur.x);
            st.y = add2(acc1[c + 1], cur.y);
            *(ulonglong2*)(op + 2 * c) = st;
        }
    }
}

// ---------------------------------------------------------------------------
// Side stream + events, created at static-init (before harness checkpoints).
// If creation fails, s_side stays 0 and everything runs on the default stream
// (still correct, just serial).
// ---------------------------------------------------------------------------
static cudaStream_t s_side = 0;
static cudaEvent_t  ev_fork = 0, ev_self = 0;
namespace {
struct StreamInit {
    StreamInit() {
        if (cudaStreamCreateWithFlags(&s_side, cudaStreamNonBlocking) != cudaSuccess) s_side = 0;
        if (cudaEventCreateWithFlags(&ev_fork, cudaEventDisableTiming) != cudaSuccess) ev_fork = 0;
        if (cudaEventCreateWithFlags(&ev_self, cudaEventDisableTiming) != cudaSuccess) ev_self = 0;
        if (!ev_fork || !ev_self) s_side = 0;   // fall back to serial
    }
};
static StreamInit s_init;
}

// ---------------------------------------------------------------------------
// launch
// ---------------------------------------------------------------------------
extern "C" void kernel_launch(void* const* d_in, const int* in_sizes, int n_in,
                              void* d_out, int out_size) {
    const float* x    = (const float*)d_in[0];
    const int*   src  = (const int*)d_in[1];
    const int*   dst  = (const int*)d_in[2];
    const float* w    = (const float*)d_in[3];
    const float* Wn   = (const float*)d_in[4];
    const float* Ws   = (const float*)d_in[5];
    const float* bias = (const float*)d_in[6];
    float* out = (float*)d_out;

    const int n = in_sizes[0] / D;
    const int E = in_sizes[3];
    const int blk = 256;
    const int ggrid = (n + BM - 1) / BM;

    // fork: self_gemm on side stream, concurrent with CSR build + aggregation
    if (s_side) {
        cudaEventRecord(ev_fork, 0);
        cudaStreamWaitEvent(s_side, ev_fork, 0);
        self_gemm_kernel<<<ggrid, 256, 0, s_side>>>(x, Ws, bias, out, n);
        cudaEventRecord(ev_self, s_side);
    } else {
        self_gemm_kernel<<<ggrid, 256>>>(x, Ws, bias, out, n);
    }

    // main chain: CSR build -> aggregation
    zero_cnt_kernel<<<(n + blk - 1) / blk, blk>>>(src, n);
    hist_kernel<<<(E + blk - 1) / blk, blk>>>(dst, E);
    scan_kernel<<<1, 1024>>>(n, E);
    {
        int nt = (E + 1) / 2;
        scatter_kernel<<<(nt + blk - 1) / blk, blk>>>(src, dst, w, E);
    }
    {
        int warps_per_blk = blk / 32;
        int grid = (n + warps_per_blk - 1) / warps_per_blk;
        agg_kernel<<<grid, blk>>>(x, n);
    }

    // join: nbrs_gemm needs both agg (this stream) and self_gemm's out
    if (s_side) cudaStreamWaitEvent(0, ev_self, 0);
    nbrs_gemm_kernel<<<ggrid, 256>>>(Wn, out, n);
}

// round 6
// speedup vs baseline: 1.3987x; 1.3384x over previous
#include <cuda_runtime.h>
#include <cstdint>
#include <cstddef>

#define D 128
#define MAXN 100000
#define MAXE 1600000
#define BM 64
#define RSTR 66          // float stride: row-pairs are 8B-aligned & LDS.64 conflict-free
#define SCHUNK 1024      // elements per scan block

typedef unsigned long long u64;

// ---------------------------------------------------------------------------
// Device scratch (static; allocation-guard-safe)
// ---------------------------------------------------------------------------
__device__ float g_agg[(size_t)MAXN * D];      // aggregated neighbor rows
__device__ u64   g_edges[MAXE];                // packed (w<<32 | src), CSR order
__device__ int   g_cnt[MAXN];
__device__ int   g_row[MAXN + 1];
__device__ int   g_cur[MAXN];
__device__ int   g_bsum[256];                  // per-chunk block sums
__device__ int   g_is64;

// ---------------------------------------------------------------------------
// f32x2 helpers
// ---------------------------------------------------------------------------
__device__ __forceinline__ u64 dup2(float f) {
    u64 r; unsigned u = __float_as_uint(f);
    asm("mov.b64 %0, {%1, %1};" : "=l"(r) : "r"(u));
    return r;
}
__device__ __forceinline__ void ffma2(u64& d, u64 a, u64 b) {
    asm("fma.rn.f32x2 %0, %1, %2, %0;" : "+l"(d) : "l"(a), "l"(b));
}
__device__ __forceinline__ u64 add2(u64 a, u64 b) {
    u64 r;
    asm("add.rn.f32x2 %0, %1, %2;" : "=l"(r) : "l"(a), "l"(b));
    return r;
}
__device__ __forceinline__ float2 split2(u64 v) {
    unsigned lo, hi;
    asm("mov.b64 {%0, %1}, %2;" : "=r"(lo), "=r"(hi) : "l"(v));
    float2 r; r.x = __uint_as_float(lo); r.y = __uint_as_float(hi);
    return r;
}

// ---------------------------------------------------------------------------
// CSR build
// ---------------------------------------------------------------------------
__global__ void zero_cnt_kernel(const int* __restrict__ idx_raw, int n) {
    int i = blockIdx.x * blockDim.x + threadIdx.x;
    if (i < n) g_cnt[i] = 0;
    if (i == 0) {
        unsigned o = 0;
        #pragma unroll
        for (int j = 0; j < 16; j++) o |= (unsigned)idx_raw[2 * j + 1];
        g_is64 = (o == 0u) ? 1 : 0;
    }
}

__global__ void hist_kernel(const int* __restrict__ dst_raw, int E) {
    const bool is64 = (g_is64 != 0);
    int e = blockIdx.x * blockDim.x + threadIdx.x;
    if (e >= E) return;
    int d = is64 ? (int)((const long long*)dst_raw)[e] : dst_raw[e];
    atomicAdd(&g_cnt[d], 1);
}

// -- scan phase 1: per-block scan of SCHUNK elements (256 thr x 4/thread) ----
__global__ void __launch_bounds__(256) partial_scan_kernel(int n) {
    __shared__ int wsum[8];
    const int tid  = threadIdx.x;
    const int lane = tid & 31;
    const int wid  = tid >> 5;
    const int base = blockIdx.x * SCHUNK + tid * 4;

    int v[4];
    #pragma unroll
    for (int j = 0; j < 4; j++)
        v[j] = (base + j < n) ? g_cnt[base + j] : 0;
    int s = v[0] + v[1] + v[2] + v[3];

    // inclusive warp scan of thread sums
    int inc = s;
    #pragma unroll
    for (int off = 1; off < 32; off <<= 1) {
        int t = __shfl_up_sync(0xffffffffu, inc, off);
        if (lane >= off) inc += t;
    }
    if (lane == 31) wsum[wid] = inc;
    __syncthreads();
    if (wid == 0) {
        int wv = (lane < 8) ? wsum[lane] : 0;
        #pragma unroll
        for (int off = 1; off < 8; off <<= 1) {
            int t = __shfl_up_sync(0xffffffffu, wv, off);
            if (lane >= off) wv += t;
        }
        if (lane < 8) wsum[lane] = wv;
    }
    __syncthreads();

    int excl = inc - s + (wid > 0 ? wsum[wid - 1] : 0);  // block-local exclusive
    #pragma unroll
    for (int j = 0; j < 4; j++) {
        if (base + j < n) g_row[base + j] = excl;
        excl += v[j];
    }
    if (tid == 255) g_bsum[blockIdx.x] = wsum[7];        // block total
}

// -- scan phase 2: single small block scans the <=256 block sums -------------
__global__ void __launch_bounds__(256) bsum_scan_kernel(int nb) {
    __shared__ int sh[256];
    int tid = threadIdx.x;
    int v = (tid < nb) ? g_bsum[tid] : 0;
    sh[tid] = v;
    __syncthreads();
    for (int off = 1; off < 256; off <<= 1) {
        int t = (tid >= off) ? sh[tid - off] : 0;
        __syncthreads();
        sh[tid] += t;
        __syncthreads();
    }
    if (tid < nb) g_bsum[tid] = sh[tid] - v;             // exclusive
}

// -- scan phase 3: add chunk offsets, emit g_row/g_cur, close the row table --
__global__ void add_off_kernel(int n, int E) {
    int i = blockIdx.x * blockDim.x + threadIdx.x;
    if (i < n) {
        int r = g_row[i] + g_bsum[i >> 10];
        g_row[i] = r;
        g_cur[i] = r;
    }
    if (i == 0) g_row[n] = E;
}

__global__ void scatter_kernel(const int* __restrict__ src_raw,
                               const int* __restrict__ dst_raw,
                               const float* __restrict__ w, int E) {
    const bool is64 = (g_is64 != 0);
    int t = blockIdx.x * blockDim.x + threadIdx.x;
    int e = t * 2;
    if (e >= E) return;
    int cnt = min(2, E - e);
    #pragma unroll
    for (int j = 0; j < 2; j++) {
        if (j >= cnt) break;
        int s, d;
        if (is64) {
            s = (int)((const long long*)src_raw)[e + j];
            d = (int)((const long long*)dst_raw)[e + j];
        } else {
            s = src_raw[e + j];
            d = dst_raw[e + j];
        }
        float ww = w[e + j];
        int pos = atomicAdd(&g_cur[d], 1);
        g_edges[pos] = ((u64)__float_as_uint(ww) << 32) | (unsigned)s;
    }
}

// ---------------------------------------------------------------------------
// Aggregation: one warp per dst node, 4-deep MLP, register accumulate.
// ---------------------------------------------------------------------------
__global__ void __launch_bounds__(256) agg_kernel(const float* __restrict__ x, int n) {
    const int warp = (blockIdx.x * blockDim.x + threadIdx.x) >> 5;
    if (warp >= n) return;
    const int lane = threadIdx.x & 31;

    const int beg = g_row[warp];
    const int end = g_row[warp + 1];
    const float4* x4 = (const float4*)x;

    float4 a0 = make_float4(0.f, 0.f, 0.f, 0.f);
    float4 a1 = make_float4(0.f, 0.f, 0.f, 0.f);
    float4 a2 = make_float4(0.f, 0.f, 0.f, 0.f);
    float4 a3 = make_float4(0.f, 0.f, 0.f, 0.f);

    int i = beg;
    for (; i + 3 < end; i += 4) {
        u64 e0 = g_edges[i];
        u64 e1 = g_edges[i + 1];
        u64 e2 = g_edges[i + 2];
        u64 e3 = g_edges[i + 3];
        float4 v0 = __ldg(&x4[(size_t)(unsigned)e0 * (D / 4) + lane]);
        float4 v1 = __ldg(&x4[(size_t)(unsigned)e1 * (D / 4) + lane]);
        float4 v2 = __ldg(&x4[(size_t)(unsigned)e2 * (D / 4) + lane]);
        float4 v3 = __ldg(&x4[(size_t)(unsigned)e3 * (D / 4) + lane]);
        float w0 = __uint_as_float((unsigned)(e0 >> 32));
        float w1 = __uint_as_float((unsigned)(e1 >> 32));
        float w2 = __uint_as_float((unsigned)(e2 >> 32));
        float w3 = __uint_as_float((unsigned)(e3 >> 32));
        a0.x += w0 * v0.x; a0.y += w0 * v0.y; a0.z += w0 * v0.z; a0.w += w0 * v0.w;
        a1.x += w1 * v1.x; a1.y += w1 * v1.y; a1.z += w1 * v1.z; a1.w += w1 * v1.w;
        a2.x += w2 * v2.x; a2.y += w2 * v2.y; a2.z += w2 * v2.z; a2.w += w2 * v2.w;
        a3.x += w3 * v3.x; a3.y += w3 * v3.y; a3.z += w3 * v3.z; a3.w += w3 * v3.w;
    }
    for (; i < end; i++) {
        u64 e0 = g_edges[i];
        float w0 = __uint_as_float((unsigned)(e0 >> 32));
        float4 v0 = __ldg(&x4[(size_t)(unsigned)e0 * (D / 4) + lane]);
        a0.x += w0 * v0.x; a0.y += w0 * v0.y; a0.z += w0 * v0.z; a0.w += w0 * v0.w;
    }
    float4 r;
    r.x = (a0.x + a1.x) + (a2.x + a3.x);
    r.y = (a0.y + a1.y) + (a2.y + a3.y);
    r.z = (a0.z + a1.z) + (a2.z + a3.z);
    r.w = (a0.w + a1.w) + (a2.w + a3.w);
    ((float4*)g_agg)[(size_t)warp * (D / 4) + lane] = r;
}

// ---------------------------------------------------------------------------
// GEMM core: acc = M_tile @ W  (column-pair f32x2, warp-uniform weight LDGs)
// ---------------------------------------------------------------------------
__device__ __forceinline__ void gemm_core(
    const float* __restrict__ s_m,
    const float* __restrict__ W,
    int c0, int r0, u64 acc0[8], u64 acc1[8])
{
    #pragma unroll 2
    for (int k = 0; k < 128; k++) {
        u64 mp = *(const u64*)(s_m + k * RSTR + r0);
        float2 mv = split2(mp);
        u64 M0 = dup2(mv.x), M1 = dup2(mv.y);

        const ulonglong2* pw = (const ulonglong2*)(W + (size_t)k * D + c0);
        ulonglong2 w01 = __ldg(pw);
        ulonglong2 w23 = __ldg(pw + 1);
        ulonglong2 w45 = __ldg(pw + 2);
        ulonglong2 w67 = __ldg(pw + 3);

        ffma2(acc0[0], M0, w01.x); ffma2(acc1[0], M1, w01.x);
        ffma2(acc0[1], M0, w01.y); ffma2(acc1[1], M1, w01.y);
        ffma2(acc0[2], M0, w23.x); ffma2(acc1[2], M1, w23.x);
        ffma2(acc0[3], M0, w23.y); ffma2(acc1[3], M1, w23.y);
        ffma2(acc0[4], M0, w45.x); ffma2(acc1[4], M1, w45.x);
        ffma2(acc0[5], M0, w45.y); ffma2(acc1[5], M1, w45.y);
        ffma2(acc0[6], M0, w67.x); ffma2(acc1[6], M1, w67.x);
        ffma2(acc0[7], M0, w67.y); ffma2(acc1[7], M1, w67.y);
    }
}

// ---------------------------------------------------------------------------
// self_gemm: out = x @ Ws + bias          (side stream, overlaps build+agg)
// ---------------------------------------------------------------------------
__global__ void __launch_bounds__(256) self_gemm_kernel(
    const float* __restrict__ x,
    const float* __restrict__ Ws,
    const float* __restrict__ bias,
    float* __restrict__ out, int n)
{
    __shared__ float s_m[128 * RSTR];
    const int tid = threadIdx.x;
    const int row0 = blockIdx.x * BM;

    for (int idx = tid; idx < BM * D; idx += 256) {
        int r = idx >> 7;
        int k = idx & 127;
        int gr = row0 + r;
        s_m[k * RSTR + r] = (gr < n) ? x[(size_t)gr * D + k] : 0.f;
    }
    __syncthreads();

    const int c0 = (tid >> 5) * 16;
    const int r0 = (tid & 31) * 2;

    u64 acc0[8], acc1[8];
    #pragma unroll
    for (int c = 0; c < 8; c++) { acc0[c] = 0ull; acc1[c] = 0ull; }
    gemm_core(s_m, Ws, c0, r0, acc0, acc1);

    u64 b[8];
    #pragma unroll
    for (int c = 0; c < 8; c++) b[c] = *(const u64*)(bias + c0 + 2 * c);

    int rlo = row0 + r0;
    if (rlo < n) {
        float* op = out + (size_t)rlo * D + c0;
        #pragma unroll
        for (int c = 0; c < 8; c += 2) {
            ulonglong2 st;
            st.x = add2(acc0[c], b[c]);
            st.y = add2(acc0[c + 1], b[c + 1]);
            *(ulonglong2*)(op + 2 * c) = st;
        }
    }
    if (rlo + 1 < n) {
        float* op = out + (size_t)(rlo + 1) * D + c0;
        #pragma unroll
        for (int c = 0; c < 8; c += 2) {
            ulonglong2 st;
            st.x = add2(acc1[c], b[c]);
            st.y = add2(acc1[c + 1], b[c + 1]);
            *(ulonglong2*)(op + 2 * c) = st;
        }
    }
}

// ---------------------------------------------------------------------------
// nbrs_gemm: out += g_agg @ Wn
// ---------------------------------------------------------------------------
__global__ void __launch_bounds__(256) nbrs_gemm_kernel(
    const float* __restrict__ Wn,
    float* __restrict__ out, int n)
{
    __shared__ float s_m[128 * RSTR];
    const int tid = threadIdx.x;
    const int row0 = blockIdx.x * BM;

    for (int idx = tid; idx < BM * D; idx += 256) {
        int r = idx >> 7;
        int k = idx & 127;
        int gr = row0 + r;
        s_m[k * RSTR + r] = (gr < n) ? g_agg[(size_t)gr * D + k] : 0.f;
    }
    __syncthreads();

    const int c0 = (tid >> 5) * 16;
    const int r0 = (tid & 31) * 2;

    u64 acc0[8], acc1[8];
    #pragma unroll
    for (int c = 0; c < 8; c++) { acc0[c] = 0ull; acc1[c] = 0ull; }
    gemm_core(s_m, Wn, c0, r0, acc0, acc1);

    int rlo = row0 + r0;
    if (rlo < n) {
        float* op = out + (size_t)rlo * D + c0;
        #pragma unroll
        for (int c = 0; c < 8; c += 2) {
            ulonglong2 cur = *(const ulonglong2*)(op + 2 * c);
            ulonglong2 st;
            st.x = add2(acc0[c], cur.x);
            st.y = add2(acc0[c + 1], cur.y);
            *(ulonglong2*)(op + 2 * c) = st;
        }
    }
    if (rlo + 1 < n) {
        float* op = out + (size_t)(rlo + 1) * D + c0;
        #pragma unroll
        for (int c = 0; c < 8; c += 2) {
            ulonglong2 cur = *(const ulonglong2*)(op + 2 * c);
            ulonglong2 st;
            st.x = add2(acc1[c], cur.x);
            st.y = add2(acc1[c + 1], cur.y);
            *(ulonglong2*)(op + 2 * c) = st;
        }
    }
}

// ---------------------------------------------------------------------------
// Side stream + events (static-init; falls back to serial if creation fails)
// ---------------------------------------------------------------------------
static cudaStream_t s_side = 0;
static cudaEvent_t  ev_fork = 0, ev_self = 0;
namespace {
struct StreamInit {
    StreamInit() {
        if (cudaStreamCreateWithFlags(&s_side, cudaStreamNonBlocking) != cudaSuccess) s_side = 0;
        if (cudaEventCreateWithFlags(&ev_fork, cudaEventDisableTiming) != cudaSuccess) ev_fork = 0;
        if (cudaEventCreateWithFlags(&ev_self, cudaEventDisableTiming) != cudaSuccess) ev_self = 0;
        if (!ev_fork || !ev_self) s_side = 0;
    }
};
static StreamInit s_init;
}

// ---------------------------------------------------------------------------
// launch
// ---------------------------------------------------------------------------
extern "C" void kernel_launch(void* const* d_in, const int* in_sizes, int n_in,
                              void* d_out, int out_size) {
    const float* x    = (const float*)d_in[0];
    const int*   src  = (const int*)d_in[1];
    const int*   dst  = (const int*)d_in[2];
    const float* w    = (const float*)d_in[3];
    const float* Wn   = (const float*)d_in[4];
    const float* Ws   = (const float*)d_in[5];
    const float* bias = (const float*)d_in[6];
    float* out = (float*)d_out;

    const int n = in_sizes[0] / D;
    const int E = in_sizes[3];
    const int blk = 256;
    const int ggrid = (n + BM - 1) / BM;
    const int nb = (n + SCHUNK - 1) / SCHUNK;

    // fork: self_gemm on side stream, concurrent with CSR build + aggregation
    if (s_side) {
        cudaEventRecord(ev_fork, 0);
        cudaStreamWaitEvent(s_side, ev_fork, 0);
        self_gemm_kernel<<<ggrid, 256, 0, s_side>>>(x, Ws, bias, out, n);
        cudaEventRecord(ev_self, s_side);
    } else {
        self_gemm_kernel<<<ggrid, 256>>>(x, Ws, bias, out, n);
    }

    // main chain: CSR build -> aggregation
    zero_cnt_kernel<<<(n + blk - 1) / blk, blk>>>(src, n);
    hist_kernel<<<(E + blk - 1) / blk, blk>>>(dst, E);
    partial_scan_kernel<<<nb, 256>>>(n);
    bsum_scan_kernel<<<1, 256>>>(nb);
    add_off_kernel<<<(n + blk - 1) / blk, blk>>>(n, E);
    {
        int nt = (E + 1) / 2;
        scatter_kernel<<<(nt + blk - 1) / blk, blk>>>(src, dst, w, E);
    }
    {
        int warps_per_blk = blk / 32;
        int grid = (n + warps_per_blk - 1) / warps_per_blk;
        agg_kernel<<<grid, blk>>>(x, n);
    }

    // join: nbrs_gemm needs both agg (this stream) and self_gemm's out
    if (s_side) cudaStreamWaitEvent(0, ev_self, 0);
    nbrs_gemm_kernel<<<ggrid, 256>>>(Wn, out, n);
}

// round 7
// speedup vs baseline: 1.4119x; 1.0094x over previous
#include <cuda_runtime.h>
#include <cstdint>
#include <cstddef>

#define D 128
#define MAXN 100000
#define MAXE 1600000
#define BM 64
#define RSTR 66          // float stride: row-pairs 8B-aligned & LDS.64 conflict-free
#define SCHUNK 1024

typedef unsigned long long u64;

// ---------------------------------------------------------------------------
// Device scratch (static; allocation-guard-safe). g_cnt/g_look zero at load;
// scan1 re-zeroes g_cnt each launch; g_look uses epoch tags (no re-zero).
// ---------------------------------------------------------------------------
__device__ float g_agg[(size_t)MAXN * D];
__device__ u64   g_edges[MAXE];
__device__ int   g_cnt[MAXN];
__device__ int   g_row[MAXN + 1];
__device__ int   g_cur[MAXN];
__device__ u64   g_look[128];                  // (epoch<<32)|block_aggregate
__device__ int   g_epoch;

// ---------------------------------------------------------------------------
// f32x2 helpers
// ---------------------------------------------------------------------------
__device__ __forceinline__ u64 dup2(float f) {
    u64 r; unsigned u = __float_as_uint(f);
    asm("mov.b64 %0, {%1, %1};" : "=l"(r) : "r"(u));
    return r;
}
__device__ __forceinline__ void ffma2(u64& d, u64 a, u64 b) {
    asm("fma.rn.f32x2 %0, %1, %2, %0;" : "+l"(d) : "l"(a), "l"(b));
}
__device__ __forceinline__ u64 add2(u64 a, u64 b) {
    u64 r;
    asm("add.rn.f32x2 %0, %1, %2;" : "=l"(r) : "l"(a), "l"(b));
    return r;
}
__device__ __forceinline__ float2 split2(u64 v) {
    unsigned lo, hi;
    asm("mov.b64 {%0, %1}, %2;" : "=r"(lo), "=r"(hi) : "l"(v));
    float2 r; r.x = __uint_as_float(lo); r.y = __uint_as_float(hi);
    return r;
}

// per-block index-dtype sniff (int64 indices < 100000 → odd words all zero)
__device__ __forceinline__ bool block_sniff64(const int* p, int* s_flag) {
    if (threadIdx.x == 0) {
        unsigned o = 0;
        #pragma unroll
        for (int j = 0; j < 16; j++) o |= (unsigned)p[2 * j + 1];
        *s_flag = (o == 0u) ? 1 : 0;
    }
    __syncthreads();
    return *s_flag != 0;
}

// ---------------------------------------------------------------------------
// Launch 1: histogram (also bumps the scan epoch)
// ---------------------------------------------------------------------------
__global__ void __launch_bounds__(256) hist_kernel(const int* __restrict__ dst_raw, int E) {
    __shared__ int s_is64;
    const bool is64 = block_sniff64(dst_raw, &s_is64);
    if (blockIdx.x == 0 && threadIdx.x == 0) g_epoch = g_epoch + 1;
    int e = blockIdx.x * blockDim.x + threadIdx.x;
    if (e >= E) return;
    int d = is64 ? (int)((const long long*)dst_raw)[e] : dst_raw[e];
    atomicAdd(&g_cnt[d], 1);
}

// ---------------------------------------------------------------------------
// Launch 2: single-pass scan (decoupled lookback over <=98 blocks).
// Writes absolute g_row[0..n] (g_row[n]=E), g_cur=row, zeroes g_cnt.
// ---------------------------------------------------------------------------
__global__ void __launch_bounds__(256) scan1_kernel(int n) {
    __shared__ int wsum[8];
    __shared__ int s_red[256];
    __shared__ int s_prefix;

    const int tid  = threadIdx.x;
    const int lane = tid & 31;
    const int wid  = tid >> 5;
    const int b    = blockIdx.x;
    const int base = b * SCHUNK + tid * 4;
    const int epoch = g_epoch;

    int v[4];
    #pragma unroll
    for (int j = 0; j < 4; j++)
        v[j] = (base + j < n) ? g_cnt[base + j] : 0;
    int s = v[0] + v[1] + v[2] + v[3];

    int inc = s;
    #pragma unroll
    for (int off = 1; off < 32; off <<= 1) {
        int t = __shfl_up_sync(0xffffffffu, inc, off);
        if (lane >= off) inc += t;
    }
    if (lane == 31) wsum[wid] = inc;
    __syncthreads();
    if (wid == 0) {
        int wv = (lane < 8) ? wsum[lane] : 0;
        #pragma unroll
        for (int off = 1; off < 8; off <<= 1) {
            int t = __shfl_up_sync(0xffffffffu, wv, off);
            if (lane >= off) wv += t;
        }
        if (lane < 8) wsum[lane] = wv;
    }
    __syncthreads();

    // publish this block's aggregate with epoch tag
    if (tid == 0) {
        u64 tag = ((u64)(unsigned)epoch << 32) | (unsigned)wsum[7];
        atomicExch(&g_look[b], tag);
    }

    // lookback: thread t spins on predecessor t's aggregate, then reduce
    int myv = 0;
    if (tid < b) {
        u64 lk;
        do {
            asm volatile("ld.acquire.gpu.global.b64 %0, [%1];"
                         : "=l"(lk) : "l"(&g_look[tid]) : "memory");
        } while ((int)(lk >> 32) != epoch);
        myv = (int)(unsigned)lk;
    }
    s_red[tid] = myv;
    __syncthreads();
    for (int off = 128; off > 0; off >>= 1) {
        if (tid < off) s_red[tid] += s_red[tid + off];
        __syncthreads();
    }
    if (tid == 0) s_prefix = s_red[0];
    __syncthreads();

    int excl = inc - s + (wid > 0 ? wsum[wid - 1] : 0) + s_prefix;
    #pragma unroll
    for (int j = 0; j < 4; j++) {
        int idx = base + j;
        if (idx <= n) {
            g_row[idx] = excl;
            if (idx < n) { g_cur[idx] = excl; g_cnt[idx] = 0; }
        }
        excl += v[j];
    }
}

// ---------------------------------------------------------------------------
// Launch 3: scatter packed (w,src) into CSR order
// ---------------------------------------------------------------------------
__global__ void __launch_bounds__(256) scatter_kernel(const int* __restrict__ src_raw,
                                                      const int* __restrict__ dst_raw,
                                                      const float* __restrict__ w, int E) {
    __shared__ int s_is64;
    const bool is64 = block_sniff64(dst_raw, &s_is64);
    int t = blockIdx.x * blockDim.x + threadIdx.x;
    int e = t * 2;
    if (e >= E) return;
    int cnt = min(2, E - e);
    #pragma unroll
    for (int j = 0; j < 2; j++) {
        if (j >= cnt) break;
        int s, d;
        if (is64) {
            s = (int)((const long long*)src_raw)[e + j];
            d = (int)((const long long*)dst_raw)[e + j];
        } else {
            s = src_raw[e + j];
            d = dst_raw[e + j];
        }
        float ww = w[e + j];
        int pos = atomicAdd(&g_cur[d], 1);
        g_edges[pos] = ((u64)__float_as_uint(ww) << 32) | (unsigned)s;
    }
}

// ---------------------------------------------------------------------------
// Launch 4 (PROFILED SLOT): aggregation — warp per dst node, 4-deep MLP
// (kept identical to R6 for a clean profile)
// ---------------------------------------------------------------------------
__global__ void __launch_bounds__(256) agg_kernel(const float* __restrict__ x, int n) {
    const int warp = (blockIdx.x * blockDim.x + threadIdx.x) >> 5;
    if (warp >= n) return;
    const int lane = threadIdx.x & 31;

    const int beg = g_row[warp];
    const int end = g_row[warp + 1];
    const float4* x4 = (const float4*)x;

    float4 a0 = make_float4(0.f, 0.f, 0.f, 0.f);
    float4 a1 = make_float4(0.f, 0.f, 0.f, 0.f);
    float4 a2 = make_float4(0.f, 0.f, 0.f, 0.f);
    float4 a3 = make_float4(0.f, 0.f, 0.f, 0.f);

    int i = beg;
    for (; i + 3 < end; i += 4) {
        u64 e0 = g_edges[i];
        u64 e1 = g_edges[i + 1];
        u64 e2 = g_edges[i + 2];
        u64 e3 = g_edges[i + 3];
        float4 v0 = __ldg(&x4[(size_t)(unsigned)e0 * (D / 4) + lane]);
        float4 v1 = __ldg(&x4[(size_t)(unsigned)e1 * (D / 4) + lane]);
        float4 v2 = __ldg(&x4[(size_t)(unsigned)e2 * (D / 4) + lane]);
        float4 v3 = __ldg(&x4[(size_t)(unsigned)e3 * (D / 4) + lane]);
        float w0 = __uint_as_float((unsigned)(e0 >> 32));
        float w1 = __uint_as_float((unsigned)(e1 >> 32));
        float w2 = __uint_as_float((unsigned)(e2 >> 32));
        float w3 = __uint_as_float((unsigned)(e3 >> 32));
        a0.x += w0 * v0.x; a0.y += w0 * v0.y; a0.z += w0 * v0.z; a0.w += w0 * v0.w;
        a1.x += w1 * v1.x; a1.y += w1 * v1.y; a1.z += w1 * v1.z; a1.w += w1 * v1.w;
        a2.x += w2 * v2.x; a2.y += w2 * v2.y; a2.z += w2 * v2.z; a2.w += w2 * v2.w;
        a3.x += w3 * v3.x; a3.y += w3 * v3.y; a3.z += w3 * v3.z; a3.w += w3 * v3.w;
    }
    for (; i < end; i++) {
        u64 e0 = g_edges[i];
        float w0 = __uint_as_float((unsigned)(e0 >> 32));
        float4 v0 = __ldg(&x4[(size_t)(unsigned)e0 * (D / 4) + lane]);
        a0.x += w0 * v0.x; a0.y += w0 * v0.y; a0.z += w0 * v0.z; a0.w += w0 * v0.w;
    }
    float4 r;
    r.x = (a0.x + a1.x) + (a2.x + a3.x);
    r.y = (a0.y + a1.y) + (a2.y + a3.y);
    r.z = (a0.z + a1.z) + (a2.z + a3.z);
    r.w = (a0.w + a1.w) + (a2.w + a3.w);
    ((float4*)g_agg)[(size_t)warp * (D / 4) + lane] = r;
}

// ---------------------------------------------------------------------------
// GEMM core: acc = M_tile @ W  (column-pair f32x2, warp-uniform weight LDGs)
// ---------------------------------------------------------------------------
__device__ __forceinline__ void gemm_core(
    const float* __restrict__ s_m,
    const float* __restrict__ W,
    int c0, int r0, u64 acc0[8], u64 acc1[8])
{
    #pragma unroll 2
    for (int k = 0; k < 128; k++) {
        u64 mp = *(const u64*)(s_m + k * RSTR + r0);
        float2 mv = split2(mp);
        u64 M0 = dup2(mv.x), M1 = dup2(mv.y);

        const ulonglong2* pw = (const ulonglong2*)(W + (size_t)k * D + c0);
        ulonglong2 w01 = __ldg(pw);
        ulonglong2 w23 = __ldg(pw + 1);
        ulonglong2 w45 = __ldg(pw + 2);
        ulonglong2 w67 = __ldg(pw + 3);

        ffma2(acc0[0], M0, w01.x); ffma2(acc1[0], M1, w01.x);
        ffma2(acc0[1], M0, w01.y); ffma2(acc1[1], M1, w01.y);
        ffma2(acc0[2], M0, w23.x); ffma2(acc1[2], M1, w23.x);
        ffma2(acc0[3], M0, w23.y); ffma2(acc1[3], M1, w23.y);
        ffma2(acc0[4], M0, w45.x); ffma2(acc1[4], M1, w45.x);
        ffma2(acc0[5], M0, w45.y); ffma2(acc1[5], M1, w45.y);
        ffma2(acc0[6], M0, w67.x); ffma2(acc1[6], M1, w67.x);
        ffma2(acc0[7], M0, w67.y); ffma2(acc1[7], M1, w67.y);
    }
}

// ---------------------------------------------------------------------------
// self_gemm: out = x @ Ws + bias      (side stream; executes from t=0)
// ---------------------------------------------------------------------------
__global__ void __launch_bounds__(256) self_gemm_kernel(
    const float* __restrict__ x,
    const float* __restrict__ Ws,
    const float* __restrict__ bias,
    float* __restrict__ out, int n)
{
    __shared__ float s_m[128 * RSTR];
    const int tid = threadIdx.x;
    const int row0 = blockIdx.x * BM;

    for (int idx = tid; idx < BM * D; idx += 256) {
        int r = idx >> 7;
        int k = idx & 127;
        int gr = row0 + r;
        s_m[k * RSTR + r] = (gr < n) ? x[(size_t)gr * D + k] : 0.f;
    }
    __syncthreads();

    const int c0 = (tid >> 5) * 16;
    const int r0 = (tid & 31) * 2;

    u64 acc0[8], acc1[8];
    #pragma unroll
    for (int c = 0; c < 8; c++) { acc0[c] = 0ull; acc1[c] = 0ull; }
    gemm_core(s_m, Ws, c0, r0, acc0, acc1);

    u64 b[8];
    #pragma unroll
    for (int c = 0; c < 8; c++) b[c] = *(const u64*)(bias + c0 + 2 * c);

    int rlo = row0 + r0;
    if (rlo < n) {
        float* op = out + (size_t)rlo * D + c0;
        #pragma unroll
        for (int c = 0; c < 8; c += 2) {
            ulonglong2 st;
            st.x = add2(acc0[c], b[c]);
            st.y = add2(acc0[c + 1], b[c + 1]);
            *(ulonglong2*)(op + 2 * c) = st;
        }
    }
    if (rlo + 1 < n) {
        float* op = out + (size_t)(rlo + 1) * D + c0;
        #pragma unroll
        for (int c = 0; c < 8; c += 2) {
            ulonglong2 st;
            st.x = add2(acc1[c], b[c]);
            st.y = add2(acc1[c + 1], b[c + 1]);
            *(ulonglong2*)(op + 2 * c) = st;
        }
    }
}

// ---------------------------------------------------------------------------
// nbrs_gemm: out += g_agg @ Wn
// ---------------------------------------------------------------------------
__global__ void __launch_bounds__(256) nbrs_gemm_kernel(
    const float* __restrict__ Wn,
    float* __restrict__ out, int n)
{
    __shared__ float s_m[128 * RSTR];
    const int tid = threadIdx.x;
    const int row0 = blockIdx.x * BM;

    for (int idx = tid; idx < BM * D; idx += 256) {
        int r = idx >> 7;
        int k = idx & 127;
        int gr = row0 + r;
        s_m[k * RSTR + r] = (gr < n) ? g_agg[(size_t)gr * D + k] : 0.f;
    }
    __syncthreads();

    const int c0 = (tid >> 5) * 16;
    const int r0 = (tid & 31) * 2;

    u64 acc0[8], acc1[8];
    #pragma unroll
    for (int c = 0; c < 8; c++) { acc0[c] = 0ull; acc1[c] = 0ull; }
    gemm_core(s_m, Wn, c0, r0, acc0, acc1);

    int rlo = row0 + r0;
    if (rlo < n) {
        float* op = out + (size_t)rlo * D + c0;
        #pragma unroll
        for (int c = 0; c < 8; c += 2) {
            ulonglong2 cur = *(const ulonglong2*)(op + 2 * c);
            ulonglong2 st;
            st.x = add2(acc0[c], cur.x);
            st.y = add2(acc0[c + 1], cur.y);
            *(ulonglong2*)(op + 2 * c) = st;
        }
    }
    if (rlo + 1 < n) {
        float* op = out + (size_t)(rlo + 1) * D + c0;
        #pragma unroll
        for (int c = 0; c < 8; c += 2) {
            ulonglong2 cur = *(const ulonglong2*)(op + 2 * c);
            ulonglong2 st;
            st.x = add2(acc1[c], cur.x);
            st.y = add2(acc1[c + 1], cur.y);
            *(ulonglong2*)(op + 2 * c) = st;
        }
    }
}

// ---------------------------------------------------------------------------
// Side stream + events (static-init; serial fallback if creation fails)
// ---------------------------------------------------------------------------
static cudaStream_t s_side = 0;
static cudaEvent_t  ev_fork = 0, ev_self = 0;
namespace {
struct StreamInit {
    StreamInit() {
        if (cudaStreamCreateWithFlags(&s_side, cudaStreamNonBlocking) != cudaSuccess) s_side = 0;
        if (cudaEventCreateWithFlags(&ev_fork, cudaEventDisableTiming) != cudaSuccess) ev_fork = 0;
        if (cudaEventCreateWithFlags(&ev_self, cudaEventDisableTiming) != cudaSuccess) ev_self = 0;
        if (!ev_fork || !ev_self) s_side = 0;
    }
};
static StreamInit s_init;
}

// ---------------------------------------------------------------------------
// launch
// ---------------------------------------------------------------------------
extern "C" void kernel_launch(void* const* d_in, const int* in_sizes, int n_in,
                              void* d_out, int out_size) {
    const float* x    = (const float*)d_in[0];
    const int*   src  = (const int*)d_in[1];
    const int*   dst  = (const int*)d_in[2];
    const float* w    = (const float*)d_in[3];
    const float* Wn   = (const float*)d_in[4];
    const float* Ws   = (const float*)d_in[5];
    const float* bias = (const float*)d_in[6];
    float* out = (float*)d_out;

    const int n = in_sizes[0] / D;
    const int E = in_sizes[3];
    const int blk = 256;
    const int ggrid = (n + BM - 1) / BM;
    const int nb = ((n + 1) + SCHUNK - 1) / SCHUNK;

    if (s_side) cudaEventRecord(ev_fork, 0);   // fork point: side stream may start now

    // main chain (issue order => ncu slot): hist(1) scan1(2) scatter(3) agg(4)
    hist_kernel<<<(E + blk - 1) / blk, blk>>>(dst, E);
    scan1_kernel<<<nb, 256>>>(n);
    {
        int nt = (E + 1) / 2;
        scatter_kernel<<<(nt + blk - 1) / blk, blk>>>(src, dst, w, E);
    }
    {
        int warps_per_blk = blk / 32;
        int grid = (n + warps_per_blk - 1) / warps_per_blk;
        agg_kernel<<<grid, blk>>>(x, n);
    }

    // self_gemm: issued 5th, but executes from t=0 on the side stream
    if (s_side) {
        cudaStreamWaitEvent(s_side, ev_fork, 0);
        self_gemm_kernel<<<ggrid, 256, 0, s_side>>>(x, Ws, bias, out, n);
        cudaEventRecord(ev_self, s_side);
        cudaStreamWaitEvent(0, ev_self, 0);
    } else {
        self_gemm_kernel<<<ggrid, 256>>>(x, Ws, bias, out, n);
    }

    nbrs_gemm_kernel<<<ggrid, 256>>>(Wn, out, n);
}

// round 8
// speedup vs baseline: 1.4421x; 1.0214x over previous
#include <cuda_runtime.h>
#include <cstdint>
#include <cstddef>

#define D 128
#define MAXN 100000
#define MAXE 1600000
#define BM 64
#define RSTR 66          // float stride: row-pairs 8B-aligned, LDS.64 conflict-free
#define SCHUNK 1024

typedef unsigned long long u64;

// ---------------------------------------------------------------------------
// Device scratch (static; allocation-guard-safe). g_cnt/g_look zero at load;
// scan1 re-zeroes g_cnt after reading; g_look uses epoch tags.
// ---------------------------------------------------------------------------
__device__ float g_agg[(size_t)MAXN * D];
__device__ u64   g_edges[MAXE];
__device__ int   g_cnt[MAXN];
__device__ int   g_row[MAXN + 1];
__device__ int   g_cur[MAXN];
__device__ u64   g_look[128];                  // (epoch<<32)|block_aggregate
__device__ int   g_epoch;

// ---------------------------------------------------------------------------
// f32x2 helpers
// ---------------------------------------------------------------------------
__device__ __forceinline__ u64 dup2(float f) {
    u64 r; unsigned u = __float_as_uint(f);
    asm("mov.b64 %0, {%1, %1};" : "=l"(r) : "r"(u));
    return r;
}
__device__ __forceinline__ void ffma2(u64& d, u64 a, u64 b) {
    asm("fma.rn.f32x2 %0, %1, %2, %0;" : "+l"(d) : "l"(a), "l"(b));
}
__device__ __forceinline__ u64 add2(u64 a, u64 b) {
    u64 r;
    asm("add.rn.f32x2 %0, %1, %2;" : "=l"(r) : "l"(a), "l"(b));
    return r;
}

// per-block index-dtype sniff (int64 indices < 100000 → odd words all zero)
__device__ __forceinline__ bool block_sniff64(const int* p, int* s_flag) {
    if (threadIdx.x == 0) {
        unsigned o = 0;
        #pragma unroll
        for (int j = 0; j < 16; j++) o |= (unsigned)p[2 * j + 1];
        *s_flag = (o == 0u) ? 1 : 0;
    }
    __syncthreads();
    return *s_flag != 0;
}

// ---------------------------------------------------------------------------
// Launch 1: histogram (+ epoch bump)
// ---------------------------------------------------------------------------
__global__ void __launch_bounds__(256) hist_kernel(const int* __restrict__ dst_raw, int E) {
    __shared__ int s_is64;
    const bool is64 = block_sniff64(dst_raw, &s_is64);
    if (blockIdx.x == 0 && threadIdx.x == 0) g_epoch = g_epoch + 1;
    int e = blockIdx.x * blockDim.x + threadIdx.x;
    if (e >= E) return;
    int d = is64 ? (int)((const long long*)dst_raw)[e] : dst_raw[e];
    atomicAdd(&g_cnt[d], 1);
}

// ---------------------------------------------------------------------------
// Launch 2: single-pass scan (decoupled lookback, <=98 blocks)
// ---------------------------------------------------------------------------
__global__ void __launch_bounds__(256) scan1_kernel(int n) {
    __shared__ int wsum[8];
    __shared__ int s_red[256];
    __shared__ int s_prefix;

    const int tid  = threadIdx.x;
    const int lane = tid & 31;
    const int wid  = tid >> 5;
    const int b    = blockIdx.x;
    const int base = b * SCHUNK + tid * 4;
    const int epoch = g_epoch;

    int v[4];
    #pragma unroll
    for (int j = 0; j < 4; j++)
        v[j] = (base + j < n) ? g_cnt[base + j] : 0;
    int s = v[0] + v[1] + v[2] + v[3];

    int inc = s;
    #pragma unroll
    for (int off = 1; off < 32; off <<= 1) {
        int t = __shfl_up_sync(0xffffffffu, inc, off);
        if (lane >= off) inc += t;
    }
    if (lane == 31) wsum[wid] = inc;
    __syncthreads();
    if (wid == 0) {
        int wv = (lane < 8) ? wsum[lane] : 0;
        #pragma unroll
        for (int off = 1; off < 8; off <<= 1) {
            int t = __shfl_up_sync(0xffffffffu, wv, off);
            if (lane >= off) wv += t;
        }
        if (lane < 8) wsum[lane] = wv;
    }
    __syncthreads();

    if (tid == 0) {
        u64 tag = ((u64)(unsigned)epoch << 32) | (unsigned)wsum[7];
        atomicExch(&g_look[b], tag);
    }

    int myv = 0;
    if (tid < b) {
        u64 lk;
        do {
            asm volatile("ld.acquire.gpu.global.b64 %0, [%1];"
                         : "=l"(lk) : "l"(&g_look[tid]) : "memory");
        } while ((int)(lk >> 32) != epoch);
        myv = (int)(unsigned)lk;
    }
    s_red[tid] = myv;
    __syncthreads();
    for (int off = 128; off > 0; off >>= 1) {
        if (tid < off) s_red[tid] += s_red[tid + off];
        __syncthreads();
    }
    if (tid == 0) s_prefix = s_red[0];
    __syncthreads();

    int excl = inc - s + (wid > 0 ? wsum[wid - 1] : 0) + s_prefix;
    #pragma unroll
    for (int j = 0; j < 4; j++) {
        int idx = base + j;
        if (idx <= n) {
            g_row[idx] = excl;
            if (idx < n) { g_cur[idx] = excl; g_cnt[idx] = 0; }
        }
        excl += v[j];
    }
}

// ---------------------------------------------------------------------------
// Launch 3: scatter packed (w,src) into CSR order
// ---------------------------------------------------------------------------
__global__ void __launch_bounds__(256) scatter_kernel(const int* __restrict__ src_raw,
                                                      const int* __restrict__ dst_raw,
                                                      const float* __restrict__ w, int E) {
    __shared__ int s_is64;
    const bool is64 = block_sniff64(dst_raw, &s_is64);
    int t = blockIdx.x * blockDim.x + threadIdx.x;
    int e = t * 2;
    if (e >= E) return;
    int cnt = min(2, E - e);
    #pragma unroll
    for (int j = 0; j < 2; j++) {
        if (j >= cnt) break;
        int s, d;
        if (is64) {
            s = (int)((const long long*)src_raw)[e + j];
            d = (int)((const long long*)dst_raw)[e + j];
        } else {
            s = src_raw[e + j];
            d = dst_raw[e + j];
        }
        float ww = w[e + j];
        int pos = atomicAdd(&g_cur[d], 1);
        g_edges[pos] = ((u64)__float_as_uint(ww) << 32) | (unsigned)s;
    }
}

// ---------------------------------------------------------------------------
// Launch 4 (PROFILED SLOT, control — unchanged from R7): aggregation
// ---------------------------------------------------------------------------
__global__ void __launch_bounds__(256) agg_kernel(const float* __restrict__ x, int n) {
    const int warp = (blockIdx.x * blockDim.x + threadIdx.x) >> 5;
    if (warp >= n) return;
    const int lane = threadIdx.x & 31;

    const int beg = g_row[warp];
    const int end = g_row[warp + 1];
    const float4* x4 = (const float4*)x;

    float4 a0 = make_float4(0.f, 0.f, 0.f, 0.f);
    float4 a1 = make_float4(0.f, 0.f, 0.f, 0.f);
    float4 a2 = make_float4(0.f, 0.f, 0.f, 0.f);
    float4 a3 = make_float4(0.f, 0.f, 0.f, 0.f);

    int i = beg;
    for (; i + 3 < end; i += 4) {
        u64 e0 = g_edges[i];
        u64 e1 = g_edges[i + 1];
        u64 e2 = g_edges[i + 2];
        u64 e3 = g_edges[i + 3];
        float4 v0 = __ldg(&x4[(size_t)(unsigned)e0 * (D / 4) + lane]);
        float4 v1 = __ldg(&x4[(size_t)(unsigned)e1 * (D / 4) + lane]);
        float4 v2 = __ldg(&x4[(size_t)(unsigned)e2 * (D / 4) + lane]);
        float4 v3 = __ldg(&x4[(size_t)(unsigned)e3 * (D / 4) + lane]);
        float w0 = __uint_as_float((unsigned)(e0 >> 32));
        float w1 = __uint_as_float((unsigned)(e1 >> 32));
        float w2 = __uint_as_float((unsigned)(e2 >> 32));
        float w3 = __uint_as_float((unsigned)(e3 >> 32));
        a0.x += w0 * v0.x; a0.y += w0 * v0.y; a0.z += w0 * v0.z; a0.w += w0 * v0.w;
        a1.x += w1 * v1.x; a1.y += w1 * v1.y; a1.z += w1 * v1.z; a1.w += w1 * v1.w;
        a2.x += w2 * v2.x; a2.y += w2 * v2.y; a2.z += w2 * v2.z; a2.w += w2 * v2.w;
        a3.x += w3 * v3.x; a3.y += w3 * v3.y; a3.z += w3 * v3.z; a3.w += w3 * v3.w;
    }
    for (; i < end; i++) {
        u64 e0 = g_edges[i];
        float w0 = __uint_as_float((unsigned)(e0 >> 32));
        float4 v0 = __ldg(&x4[(size_t)(unsigned)e0 * (D / 4) + lane]);
        a0.x += w0 * v0.x; a0.y += w0 * v0.y; a0.z += w0 * v0.z; a0.w += w0 * v0.w;
    }
    float4 r;
    r.x = (a0.x + a1.x) + (a2.x + a3.x);
    r.y = (a0.y + a1.y) + (a2.y + a3.y);
    r.z = (a0.z + a1.z) + (a2.z + a3.z);
    r.w = (a0.w + a1.w) + (a2.w + a3.w);
    ((float4*)g_agg)[(size_t)warp * (D / 4) + lane] = r;
}

// ---------------------------------------------------------------------------
// Launch 5: dual GEMM  out = agg @ Wn + x @ Ws + bias   (single pass)
// Column-pair f32x2: acc u64 = {out[r][c], out[r][c+1]}. Weights consumed as
// natural u64 pairs (zero per-k weight MOVs). warp = 16 cols, lane = row pair.
// Smem 67.6 KB -> 2 blocks/SM.
// ---------------------------------------------------------------------------
__global__ void __launch_bounds__(256, 2) dual_gemm_kernel(
    const float* __restrict__ x,
    const float* __restrict__ Wn,
    const float* __restrict__ Ws,
    const float* __restrict__ bias,
    float* __restrict__ out, int n)
{
    extern __shared__ float sm[];
    float* s_a = sm;                  // [128][RSTR] agg tile
    float* s_x = sm + 128 * RSTR;     // x tile

    const int tid = threadIdx.x;
    const int row0 = blockIdx.x * BM;

    for (int idx = tid; idx < BM * D; idx += 256) {
        int r = idx >> 7;
        int k = idx & 127;
        int gr = row0 + r;
        float av = 0.f, xv = 0.f;
        if (gr < n) {
            av = g_agg[(size_t)gr * D + k];
            xv = x[(size_t)gr * D + k];
        }
        s_a[k * RSTR + r] = av;
        s_x[k * RSTR + r] = xv;
    }
    __syncthreads();

    const int c0 = (tid >> 5) * 16;   // warp -> 16-col slab
    const int r0 = (tid & 31) * 2;    // lane -> row pair

    u64 acc0[8], acc1[8];             // rows r0 / r0+1
    #pragma unroll
    for (int c = 0; c < 8; c++) { acc0[c] = 0ull; acc1[c] = 0ull; }

    #pragma unroll 2
    for (int k = 0; k < 128; k++) {
        float2 ap = *(const float2*)(s_a + k * RSTR + r0);
        float2 xp = *(const float2*)(s_x + k * RSTR + r0);
        u64 A0 = dup2(ap.x), A1 = dup2(ap.y);
        u64 X0 = dup2(xp.x), X1 = dup2(xp.y);

        const ulonglong2* pn = (const ulonglong2*)(Wn + (size_t)k * D + c0);
        const ulonglong2* ps = (const ulonglong2*)(Ws + (size_t)k * D + c0);
        ulonglong2 n01 = __ldg(pn);
        ulonglong2 n23 = __ldg(pn + 1);
        ulonglong2 n45 = __ldg(pn + 2);
        ulonglong2 n67 = __ldg(pn + 3);
        ulonglong2 s01 = __ldg(ps);
        ulonglong2 s23 = __ldg(ps + 1);
        ulonglong2 s45 = __ldg(ps + 2);
        ulonglong2 s67 = __ldg(ps + 3);

        ffma2(acc0[0], A0, n01.x); ffma2(acc0[0], X0, s01.x);
        ffma2(acc0[1], A0, n01.y); ffma2(acc0[1], X0, s01.y);
        ffma2(acc0[2], A0, n23.x); ffma2(acc0[2], X0, s23.x);
        ffma2(acc0[3], A0, n23.y); ffma2(acc0[3], X0, s23.y);
        ffma2(acc0[4], A0, n45.x); ffma2(acc0[4], X0, s45.x);
        ffma2(acc0[5], A0, n45.y); ffma2(acc0[5], X0, s45.y);
        ffma2(acc0[6], A0, n67.x); ffma2(acc0[6], X0, s67.x);
        ffma2(acc0[7], A0, n67.y); ffma2(acc0[7], X0, s67.y);

        ffma2(acc1[0], A1, n01.x); ffma2(acc1[0], X1, s01.x);
        ffma2(acc1[1], A1, n01.y); ffma2(acc1[1], X1, s01.y);
        ffma2(acc1[2], A1, n23.x); ffma2(acc1[2], X1, s23.x);
        ffma2(acc1[3], A1, n23.y); ffma2(acc1[3], X1, s23.y);
        ffma2(acc1[4], A1, n45.x); ffma2(acc1[4], X1, s45.x);
        ffma2(acc1[5], A1, n45.y); ffma2(acc1[5], X1, s45.y);
        ffma2(acc1[6], A1, n67.x); ffma2(acc1[6], X1, s67.x);
        ffma2(acc1[7], A1, n67.y); ffma2(acc1[7], X1, s67.y);
    }

    u64 b[8];
    #pragma unroll
    for (int c = 0; c < 8; c++) b[c] = *(const u64*)(bias + c0 + 2 * c);

    int rlo = row0 + r0;
    if (rlo < n) {
        float* op = out + (size_t)rlo * D + c0;
        #pragma unroll
        for (int c = 0; c < 8; c += 2) {
            ulonglong2 st;
            st.x = add2(acc0[c], b[c]);
            st.y = add2(acc0[c + 1], b[c + 1]);
            *(ulonglong2*)(op + 2 * c) = st;
        }
    }
    if (rlo + 1 < n) {
        float* op = out + (size_t)(rlo + 1) * D + c0;
        #pragma unroll
        for (int c = 0; c < 8; c += 2) {
            ulonglong2 st;
            st.x = add2(acc1[c], b[c]);
            st.y = add2(acc1[c + 1], b[c + 1]);
            *(ulonglong2*)(op + 2 * c) = st;
        }
    }
}

// ---------------------------------------------------------------------------
// launch: hist(1) scan1(2) scatter(3) agg(4=profiled) dual_gemm(5)
// ---------------------------------------------------------------------------
extern "C" void kernel_launch(void* const* d_in, const int* in_sizes, int n_in,
                              void* d_out, int out_size) {
    const float* x    = (const float*)d_in[0];
    const int*   src  = (const int*)d_in[1];
    const int*   dst  = (const int*)d_in[2];
    const float* w    = (const float*)d_in[3];
    const float* Wn   = (const float*)d_in[4];
    const float* Ws   = (const float*)d_in[5];
    const float* bias = (const float*)d_in[6];
    float* out = (float*)d_out;

    const int n = in_sizes[0] / D;
    const int E = in_sizes[3];
    const int blk = 256;
    const int nb = ((n + 1) + SCHUNK - 1) / SCHUNK;

    hist_kernel<<<(E + blk - 1) / blk, blk>>>(dst, E);
    scan1_kernel<<<nb, 256>>>(n);
    {
        int nt = (E + 1) / 2;
        scatter_kernel<<<(nt + blk - 1) / blk, blk>>>(src, dst, w, E);
    }
    {
        int warps_per_blk = blk / 32;
        int grid = (n + warps_per_blk - 1) / warps_per_blk;
        agg_kernel<<<grid, blk>>>(x, n);
    }
    {
        size_t smem = 2ull * 128 * RSTR * sizeof(float);  // 67,584 B
        cudaFuncSetAttribute(dual_gemm_kernel,
                             cudaFuncAttributeMaxDynamicSharedMemorySize,
                             (int)smem);
        int grid = (n + BM - 1) / BM;
        dual_gemm_kernel<<<grid, 256, smem>>>(x, Wn, Ws, bias, out, n);
    }
}